// round 13
// baseline (speedup 1.0000x reference)
#include <cuda_runtime.h>
#include <cstdint>

// PPEG: out[b,0,c] = x[b,0,c] (cls); out[b,1+p,c] = folded 7x7 depthwise conv
// (w7 + pad(w5) + pad(w3) + identity, bias b7+b5+b3) over the 64x64 map.
// R13 = R12 (BY=2 tiles per CTA) + __launch_bounds__(128,5): 102-reg ceiling
// forbids ptxas from software-pipelining the half loop (R12 ballooned to 200
// regs / 11% occ). Forces serial halves -> L1 reuse of the 4 shared rows.

#define CH   512
#define HW   64
#define NTOK 4097

typedef unsigned long long ULL;

__device__ float g_weff[49 * CH];   // [tap][channel]
__device__ float g_bsum[CH];

// packed f32x2 FMA (sm_103a FFMA2 — only reachable via PTX)
__device__ __forceinline__ ULL ffma2(ULL a, ULL b, ULL c) {
    ULL d;
    asm("fma.rn.f32x2 %0, %1, %2, %3;" : "=l"(d) : "l"(a), "l"(b), "l"(c));
    return d;
}

// ---------------------------------------------------------------------------
// Kernel 1: weight fold + bias + cls copy, one launch.
__global__ void ppeg_prep(const float* __restrict__ w7, const float* __restrict__ b7,
                          const float* __restrict__ w5, const float* __restrict__ b5,
                          const float* __restrict__ w3, const float* __restrict__ b3,
                          const float* __restrict__ x, float* __restrict__ out) {
    const int bid = blockIdx.x;
    const int tid = threadIdx.x;
    if (bid < 98) {
        const int i = bid * 256 + tid;        // 0 .. 25087 = 512*49
        const int c = i / 49;
        const int t = i % 49;
        const int ky = t / 7, kx = t % 7;
        float v = w7[c * 49 + t];
        if (ky >= 1 && ky <= 5 && kx >= 1 && kx <= 5)
            v += w5[c * 25 + (ky - 1) * 5 + (kx - 1)];
        if (ky >= 2 && ky <= 4 && kx >= 2 && kx <= 4)
            v += w3[c * 9 + (ky - 2) * 3 + (kx - 2)];
        if (t == 24) v += 1.0f;               // identity (residual) term
        g_weff[t * CH + c] = v;
    } else if (bid < 100) {
        const int c = (bid - 98) * 256 + tid;
        g_bsum[c] = b7[c] + b5[c] + b3[c];
    } else {
        const int j = (bid - 100) * 256 + tid;   // cls: 16*512 floats
        const int b = j >> 9;
        const int cc = j & 511;
        const size_t off = (size_t)b * NTOK * CH + cc;
        out[off] = x[off];
    }
}

// ---------------------------------------------------------------------------
// Kernel 2: folded 7x7 depthwise conv.
//   lane   = channel pair (64 ch per block) -> 256B coalesced accesses
//   warp   = 8x2 px subtile; block = 4 warps (2x2) -> 16x4 px tile
//   BY=2   : two stacked 16x4 tiles per CTA, serialized by the 102-reg cap
__global__ void __launch_bounds__(128, 5)
ppeg_conv(const float* __restrict__ x, float* __restrict__ out) {
    const int lane = threadIdx.x & 31;
    const int warp = threadIdx.x >> 5;
    const int wx = warp & 1;
    const int wy = warp >> 1;                  // 0..1
    const int x0  = blockIdx.x * 16 + wx * 8;  // RX=8 output cols per thread
    const int byp = blockIdx.y * 8;            // CTA covers rows byp..byp+7
    const int b  = blockIdx.z >> 3;
    const int cg = blockIdx.z & 7;
    const int cb = cg * 64;
    const int c  = cb + lane * 2;

    // Stage this channel group's folded weights + bias into SMEM (coalesced).
    __shared__ __align__(16) float sw[49 * 64];
    __shared__ __align__(16) float sb[64];
    #pragma unroll
    for (int i = threadIdx.x; i < 49 * 64; i += 128) {
        const int t  = i >> 6;
        const int cc = i & 63;
        sw[i] = g_weff[t * CH + cb + cc];
    }
    if (threadIdx.x < 64) sb[threadIdx.x] = g_bsum[cb + threadIdx.x];
    __syncthreads();

    const ULL bias = *reinterpret_cast<const ULL*>(&sb[lane * 2]);

    const float* xb  = x + ((size_t)b * NTOK + 1) * CH + c;
    float* ob = out + ((size_t)b * NTOK + 1) * CH + c;
    const float* swp = &sw[lane * 2];

    // x-interior test: all 14 window cols in [0,64)  (warp-uniform)
    const bool xfull = (x0 >= 3) && (x0 + 10 < HW);

    #pragma unroll 1
    for (int half = 0; half < 2; ++half) {
        const int y0 = byp + half * 4 + wy * 2;    // RY=2 rows per thread

        ULL acc[2][8];
        #pragma unroll
        for (int ry = 0; ry < 2; ++ry)
            #pragma unroll
            for (int rx = 0; rx < 8; ++rx)
                acc[ry][rx] = bias;

        const float* wbase = xb + ((size_t)(y0 - 3) * HW + (x0 - 3)) * CH;

        // Sliding row window: 8 input rows feed the 2 output rows (RY+6).
        #pragma unroll
        for (int riy = 0; riy < 8; ++riy) {
            const int iy = y0 - 3 + riy;
            const bool yok = ((unsigned)iy < (unsigned)HW);

            ULL rw[14];
            if (yok && xfull) {
                // fast path: 14 plain LDG.64 at immediate offsets off one base
                const float* rowp = wbase + (size_t)riy * (HW * CH);
                #pragma unroll
                for (int i = 0; i < 14; ++i)
                    rw[i] = *reinterpret_cast<const ULL*>(&rowp[(size_t)i * CH]);
            } else {
                // border path: clamp + select-zero
                const float* row = xb + (size_t)iy * HW * CH;
                #pragma unroll
                for (int i = 0; i < 14; ++i) {
                    const int xc = x0 - 3 + i;
                    rw[i] = (yok && (unsigned)xc < (unsigned)HW)
                          ? *reinterpret_cast<const ULL*>(&row[(size_t)xc * CH])
                          : 0ULL;
                }
            }

            #pragma unroll
            for (int ky = 0; ky < 7; ++ky) {
                const int ry = riy - ky;       // compile-time after full unroll
                if (ry == 0 || ry == 1) {
                    #pragma unroll
                    for (int kx = 0; kx < 7; ++kx) {
                        const ULL wk = *reinterpret_cast<const ULL*>(
                            &swp[(ky * 7 + kx) * 64]);
                        #pragma unroll
                        for (int rx = 0; rx < 8; ++rx)
                            acc[ry][rx] = ffma2(rw[rx + kx], wk, acc[ry][rx]);
                    }
                }
            }
        }

        #pragma unroll
        for (int ry = 0; ry < 2; ++ry)
            #pragma unroll
            for (int rx = 0; rx < 8; ++rx) {
                const size_t p = (size_t)(y0 + ry) * HW + (x0 + rx);
                *reinterpret_cast<ULL*>(&ob[p * CH]) = acc[ry][rx];
            }
    }
}

// ---------------------------------------------------------------------------
extern "C" void kernel_launch(void* const* d_in, const int* in_sizes, int n_in,
                              void* d_out, int out_size) {
    const float* x  = (const float*)d_in[0];
    const float* w7 = (const float*)d_in[1];
    const float* b7 = (const float*)d_in[2];
    const float* w5 = (const float*)d_in[3];
    const float* b5 = (const float*)d_in[4];
    const float* w3 = (const float*)d_in[5];
    const float* b3 = (const float*)d_in[6];
    float* out = (float*)d_out;

    ppeg_prep<<<132, 256>>>(w7, b7, w5, b5, w3, b3, x, out);
    dim3 grid(4, 8, 16 * 8);                   // BY=2: CTA = two 16x4 tiles
    ppeg_conv<<<grid, 128>>>(x, out);
}

// round 14
// speedup vs baseline: 1.8426x; 1.8426x over previous
#include <cuda_runtime.h>
#include <cstdint>

// PPEG: out[b,0,c] = x[b,0,c] (cls); out[b,1+p,c] = folded 7x7 depthwise conv
// (w7 + pad(w5) + pad(w3) + identity, bias b7+b5+b3) over the 64x64 map.
// R14 = R9 frame with RX=16: thread = 16x2 px, warp = 16x2 px x 64ch,
// block = 4 warps stacked -> 16x8 tile. L1 cyc/px drops 26 -> 17 (-35%):
// x-redundancy 1.75->1.375 and weight-LDS per px halves. FMA becomes binder.

#define CH   512
#define HW   64
#define NTOK 4097

typedef unsigned long long ULL;

__device__ float g_weff[49 * CH];   // [tap][channel]
__device__ float g_bsum[CH];

// packed f32x2 FMA (sm_103a FFMA2 — only reachable via PTX)
__device__ __forceinline__ ULL ffma2(ULL a, ULL b, ULL c) {
    ULL d;
    asm("fma.rn.f32x2 %0, %1, %2, %3;" : "=l"(d) : "l"(a), "l"(b), "l"(c));
    return d;
}

// ---------------------------------------------------------------------------
// Kernel 1: weight fold + bias + cls copy, one launch.
__global__ void ppeg_prep(const float* __restrict__ w7, const float* __restrict__ b7,
                          const float* __restrict__ w5, const float* __restrict__ b5,
                          const float* __restrict__ w3, const float* __restrict__ b3,
                          const float* __restrict__ x, float* __restrict__ out) {
    const int bid = blockIdx.x;
    const int tid = threadIdx.x;
    if (bid < 98) {
        const int i = bid * 256 + tid;        // 0 .. 25087 = 512*49
        const int c = i / 49;
        const int t = i % 49;
        const int ky = t / 7, kx = t % 7;
        float v = w7[c * 49 + t];
        if (ky >= 1 && ky <= 5 && kx >= 1 && kx <= 5)
            v += w5[c * 25 + (ky - 1) * 5 + (kx - 1)];
        if (ky >= 2 && ky <= 4 && kx >= 2 && kx <= 4)
            v += w3[c * 9 + (ky - 2) * 3 + (kx - 2)];
        if (t == 24) v += 1.0f;               // identity (residual) term
        g_weff[t * CH + c] = v;
    } else if (bid < 100) {
        const int c = (bid - 98) * 256 + tid;
        g_bsum[c] = b7[c] + b5[c] + b3[c];
    } else {
        const int j = (bid - 100) * 256 + tid;   // cls: 16*512 floats
        const int b = j >> 9;
        const int cc = j & 511;
        const size_t off = (size_t)b * NTOK * CH + cc;
        out[off] = x[off];
    }
}

// ---------------------------------------------------------------------------
// Kernel 2: folded 7x7 depthwise conv.
//   lane   = channel pair (64 ch per block) -> 256B coalesced accesses
//   thread = 16x2 output pixels; 4 warps stacked -> block tile 16x8 pixels
//   grid   = (4, 8, 128); weights+bias staged once to smem
__global__ void __launch_bounds__(128, 4)
ppeg_conv(const float* __restrict__ x, float* __restrict__ out) {
    const int lane = threadIdx.x & 31;
    const int warp = threadIdx.x >> 5;         // 0..3 (vertical)
    const int x0 = blockIdx.x * 16;            // RX=16 output cols per thread
    const int y0 = blockIdx.y * 8 + warp * 2;  // RY=2 output rows per thread
    const int b  = blockIdx.z >> 3;
    const int cg = blockIdx.z & 7;
    const int cb = cg * 64;
    const int c  = cb + lane * 2;

    // Stage this channel group's folded weights + bias into SMEM (coalesced).
    __shared__ __align__(16) float sw[49 * 64];
    __shared__ __align__(16) float sb[64];
    #pragma unroll
    for (int i = threadIdx.x; i < 49 * 64; i += 128) {
        const int t  = i >> 6;
        const int cc = i & 63;
        sw[i] = g_weff[t * CH + cb + cc];
    }
    if (threadIdx.x < 64) sb[threadIdx.x] = g_bsum[cb + threadIdx.x];
    __syncthreads();

    const ULL bias = *reinterpret_cast<const ULL*>(&sb[lane * 2]);

    ULL acc[2][16];
    #pragma unroll
    for (int ry = 0; ry < 2; ++ry)
        #pragma unroll
        for (int rx = 0; rx < 16; ++rx)
            acc[ry][rx] = bias;

    const float* xb = x + ((size_t)b * NTOK + 1) * CH + c;
    const float* wbase = xb + ((size_t)(y0 - 3) * HW + (x0 - 3)) * CH;
    const float* swp = &sw[lane * 2];

    // x-interior test: all 22 window cols in [0,64)  (block-uniform)
    const bool xfull = (x0 >= 3) && (x0 + 18 < HW);

    // Sliding row window: 8 input rows feed the 2 output rows (RY+6).
    #pragma unroll
    for (int riy = 0; riy < 8; ++riy) {
        const int iy = y0 - 3 + riy;
        const bool yok = ((unsigned)iy < (unsigned)HW);

        ULL rw[22];
        if (yok && xfull) {
            // fast path: 22 plain LDG.64 at immediate offsets off one base
            const float* rowp = wbase + (size_t)riy * (HW * CH);
            #pragma unroll
            for (int i = 0; i < 22; ++i)
                rw[i] = *reinterpret_cast<const ULL*>(&rowp[(size_t)i * CH]);
        } else {
            // border path: clamp + select-zero
            const float* row = xb + (size_t)iy * HW * CH;
            #pragma unroll
            for (int i = 0; i < 22; ++i) {
                const int xc = x0 - 3 + i;
                rw[i] = (yok && (unsigned)xc < (unsigned)HW)
                      ? *reinterpret_cast<const ULL*>(&row[(size_t)xc * CH])
                      : 0ULL;
            }
        }

        #pragma unroll
        for (int ky = 0; ky < 7; ++ky) {
            const int ry = riy - ky;           // compile-time after full unroll
            if (ry == 0 || ry == 1) {
                #pragma unroll
                for (int kx = 0; kx < 7; ++kx) {
                    const ULL wk = *reinterpret_cast<const ULL*>(
                        &swp[(ky * 7 + kx) * 64]);
                    #pragma unroll
                    for (int rx = 0; rx < 16; ++rx)
                        acc[ry][rx] = ffma2(rw[rx + kx], wk, acc[ry][rx]);
                }
            }
        }
    }

    float* ob = out + ((size_t)b * NTOK + 1) * CH + c;
    #pragma unroll
    for (int ry = 0; ry < 2; ++ry)
        #pragma unroll
        for (int rx = 0; rx < 16; ++rx) {
            const size_t p = (size_t)(y0 + ry) * HW + (x0 + rx);
            *reinterpret_cast<ULL*>(&ob[p * CH]) = acc[ry][rx];
        }
}

// ---------------------------------------------------------------------------
extern "C" void kernel_launch(void* const* d_in, const int* in_sizes, int n_in,
                              void* d_out, int out_size) {
    const float* x  = (const float*)d_in[0];
    const float* w7 = (const float*)d_in[1];
    const float* b7 = (const float*)d_in[2];
    const float* w5 = (const float*)d_in[3];
    const float* b5 = (const float*)d_in[4];
    const float* w3 = (const float*)d_in[5];
    const float* b3 = (const float*)d_in[6];
    float* out = (float*)d_out;

    ppeg_prep<<<132, 256>>>(w7, b7, w5, b5, w3, b3, x, out);
    dim3 grid(4, 8, 16 * 8);                   // 16x8 tiles, RX=16
    ppeg_conv<<<grid, 128>>>(x, out);
}

// round 15
// speedup vs baseline: 1.9701x; 1.0692x over previous
#include <cuda_runtime.h>
#include <cstdint>

// PPEG: out[b,0,c] = x[b,0,c] (cls); out[b,1+p,c] = folded 7x7 depthwise conv
// (w7 + pad(w5) + pad(w3) + identity, bias b7+b5+b3) over the 64x64 map.
// R15 = R9 (best, 88.8us) + double-buffered row prefetch: issue row r+1's 14
// LDGs before computing row r, hiding L2 latency inside each warp.
// Frame identical to R9: 16x4 tile, 128 thr, smem weights, fast/border paths.

#define CH   512
#define HW   64
#define NTOK 4097

typedef unsigned long long ULL;

__device__ float g_weff[49 * CH];   // [tap][channel]
__device__ float g_bsum[CH];

// packed f32x2 FMA (sm_103a FFMA2 — only reachable via PTX)
__device__ __forceinline__ ULL ffma2(ULL a, ULL b, ULL c) {
    ULL d;
    asm("fma.rn.f32x2 %0, %1, %2, %3;" : "=l"(d) : "l"(a), "l"(b), "l"(c));
    return d;
}

// ---------------------------------------------------------------------------
// Kernel 1: weight fold + bias + cls copy, one launch.
__global__ void ppeg_prep(const float* __restrict__ w7, const float* __restrict__ b7,
                          const float* __restrict__ w5, const float* __restrict__ b5,
                          const float* __restrict__ w3, const float* __restrict__ b3,
                          const float* __restrict__ x, float* __restrict__ out) {
    const int bid = blockIdx.x;
    const int tid = threadIdx.x;
    if (bid < 98) {
        const int i = bid * 256 + tid;        // 0 .. 25087 = 512*49
        const int c = i / 49;
        const int t = i % 49;
        const int ky = t / 7, kx = t % 7;
        float v = w7[c * 49 + t];
        if (ky >= 1 && ky <= 5 && kx >= 1 && kx <= 5)
            v += w5[c * 25 + (ky - 1) * 5 + (kx - 1)];
        if (ky >= 2 && ky <= 4 && kx >= 2 && kx <= 4)
            v += w3[c * 9 + (ky - 2) * 3 + (kx - 2)];
        if (t == 24) v += 1.0f;               // identity (residual) term
        g_weff[t * CH + c] = v;
    } else if (bid < 100) {
        const int c = (bid - 98) * 256 + tid;
        g_bsum[c] = b7[c] + b5[c] + b3[c];
    } else {
        const int j = (bid - 100) * 256 + tid;   // cls: 16*512 floats
        const int b = j >> 9;
        const int cc = j & 511;
        const size_t off = (size_t)b * NTOK * CH + cc;
        out[off] = x[off];
    }
}

// ---------------------------------------------------------------------------
// Kernel 2: folded 7x7 depthwise conv with intra-warp row prefetch.
//   lane   = channel pair (64 ch per block) -> 256B coalesced accesses
//   warp   = 8x2 px subtile; block = 4 warps (2x2) -> 16x4 px tile
//   grid   = (4, 16, 128)
__global__ void __launch_bounds__(128, 4)
ppeg_conv(const float* __restrict__ x, float* __restrict__ out) {
    const int lane = threadIdx.x & 31;
    const int warp = threadIdx.x >> 5;
    const int wx = warp & 1;
    const int wy = warp >> 1;                  // 0..1
    const int x0 = blockIdx.x * 16 + wx * 8;   // RX=8 output cols per thread
    const int y0 = blockIdx.y * 4 + wy * 2;    // RY=2 output rows per thread
    const int b  = blockIdx.z >> 3;
    const int cg = blockIdx.z & 7;
    const int cb = cg * 64;
    const int c  = cb + lane * 2;

    // Stage this channel group's folded weights + bias into SMEM (coalesced).
    __shared__ __align__(16) float sw[49 * 64];
    __shared__ __align__(16) float sb[64];
    #pragma unroll
    for (int i = threadIdx.x; i < 49 * 64; i += 128) {
        const int t  = i >> 6;
        const int cc = i & 63;
        sw[i] = g_weff[t * CH + cb + cc];
    }
    if (threadIdx.x < 64) sb[threadIdx.x] = g_bsum[cb + threadIdx.x];
    __syncthreads();

    const ULL bias = *reinterpret_cast<const ULL*>(&sb[lane * 2]);

    ULL acc[2][8];
    #pragma unroll
    for (int ry = 0; ry < 2; ++ry)
        #pragma unroll
        for (int rx = 0; rx < 8; ++rx)
            acc[ry][rx] = bias;

    const float* xb = x + ((size_t)b * NTOK + 1) * CH + c;
    const float* wbase = xb + ((size_t)(y0 - 3) * HW + (x0 - 3)) * CH;
    const float* swp = &sw[lane * 2];

    // x-interior test: all 14 window cols in [0,64)  (warp-uniform)
    const bool xfull = (x0 >= 3) && (x0 + 10 < HW);

    auto load_win = [&](int riy, ULL* rw) {
        const int iy = y0 - 3 + riy;
        const bool yok = ((unsigned)iy < (unsigned)HW);
        if (yok && xfull) {
            const float* rowp = wbase + (size_t)riy * (HW * CH);
            #pragma unroll
            for (int i = 0; i < 14; ++i)
                rw[i] = *reinterpret_cast<const ULL*>(&rowp[(size_t)i * CH]);
        } else {
            const float* row = xb + (size_t)iy * HW * CH;
            #pragma unroll
            for (int i = 0; i < 14; ++i) {
                const int xc = x0 - 3 + i;
                rw[i] = (yok && (unsigned)xc < (unsigned)HW)
                      ? *reinterpret_cast<const ULL*>(&row[(size_t)xc * CH])
                      : 0ULL;
            }
        }
    };

    auto compute = [&](int riy, const ULL* rw) {
        #pragma unroll
        for (int ky = 0; ky < 7; ++ky) {
            const int ry = riy - ky;           // compile-time after full unroll
            if (ry == 0 || ry == 1) {
                #pragma unroll
                for (int kx = 0; kx < 7; ++kx) {
                    const ULL wk = *reinterpret_cast<const ULL*>(
                        &swp[(ky * 7 + kx) * 64]);
                    #pragma unroll
                    for (int rx = 0; rx < 8; ++rx)
                        acc[ry][rx] = ffma2(rw[rx + kx], wk, acc[ry][rx]);
                }
            }
        }
    };

    // Software pipeline: row r+1's loads issue before row r's compute.
    ULL rwA[14], rwB[14];
    load_win(0, rwA);
    #pragma unroll
    for (int r = 0; r < 8; ++r) {
        ULL* cur = (r & 1) ? rwB : rwA;
        ULL* nxt = (r & 1) ? rwA : rwB;
        if (r < 7) load_win(r + 1, nxt);
        compute(r, cur);
    }

    float* ob = out + ((size_t)b * NTOK + 1) * CH + c;
    #pragma unroll
    for (int ry = 0; ry < 2; ++ry)
        #pragma unroll
        for (int rx = 0; rx < 8; ++rx) {
            const size_t p = (size_t)(y0 + ry) * HW + (x0 + rx);
            *reinterpret_cast<ULL*>(&ob[p * CH]) = acc[ry][rx];
        }
}

// ---------------------------------------------------------------------------
extern "C" void kernel_launch(void* const* d_in, const int* in_sizes, int n_in,
                              void* d_out, int out_size) {
    const float* x  = (const float*)d_in[0];
    const float* w7 = (const float*)d_in[1];
    const float* b7 = (const float*)d_in[2];
    const float* w5 = (const float*)d_in[3];
    const float* b5 = (const float*)d_in[4];
    const float* w3 = (const float*)d_in[5];
    const float* b3 = (const float*)d_in[6];
    float* out = (float*)d_out;

    ppeg_prep<<<132, 256>>>(w7, b7, w5, b5, w3, b3, x, out);
    dim3 grid(4, 16, 16 * 8);                  // 16x4 tiles (R9 shape)
    ppeg_conv<<<grid, 128>>>(x, out);
}